// round 17
// baseline (speedup 1.0000x reference)
#include <cuda_runtime.h>
#include <cuda_fp16.h>
#include <math.h>
#include <stdint.h>

#define DQ 14
#define HID 32
#define DK 8
#define NS 240
#define DV 256
#define NTHREADS 512
#define TILE_M 128
#define NKSTEP 15          // 240 / 16
#define AK 248             // A smem row stride in halves (496 B)
#define BKS 248            // B smem row stride in halves (496 B)

// ---- smem layout (bytes) ----
#define SO_W1P    0            // float[32][20] (pad, 14 used)
#define SO_B1     2560         // float[32]
#define SO_W2R    2688         // float[8][36]  (pad, 32 used)
#define SO_B2     3840         // float[8]
#define SO_KEYH   3872         // half[256][8] exact sqrt2-scaled keys = 4096
#define SO_H4     7968         // float[16][4][32] = 8192
#define SO_Q8S    16160        // 2 x half[128][8] scaled q8 (double buf) = 4096
#define SO_RSP    20256        // float[4][128] partial row sums = 2048
#define SO_A      22304        // half[128][AK] = 63488 (unnormalized e)
#define SO_B      85792        // half[256][BKS] = 126976 (values, n-major)
#define SMEM_TOTAL 212768

#define BETA 2.0f
#define CLOG2E 2.88539008177792681f        // BETA * log2(e)
#define CSCALE 2.04027885f                 // BETA * log2(e) / sqrt(2)

__device__ float g_attn_scratch[262144 * NS];

// ---------------------------------------------------------------------------
__device__ __forceinline__ uint32_t smem_u32(const void* p) {
    uint32_t a;
    asm("{ .reg .u64 t; cvta.to.shared.u64 t, %1; cvt.u32.u64 %0, t; }" : "=r"(a) : "l"(p));
    return a;
}
__device__ __forceinline__ void ldsm_x2(uint32_t& r0, uint32_t& r1, uint32_t addr) {
    asm volatile("ldmatrix.sync.aligned.m8n8.x2.shared.b16 {%0,%1}, [%2];"
                 : "=r"(r0), "=r"(r1) : "r"(addr));
}
__device__ __forceinline__ void ldsm_x4(uint32_t& r0, uint32_t& r1, uint32_t& r2, uint32_t& r3,
                                        uint32_t addr) {
    asm volatile("ldmatrix.sync.aligned.m8n8.x4.shared.b16 {%0,%1,%2,%3}, [%4];"
                 : "=r"(r0), "=r"(r1), "=r"(r2), "=r"(r3) : "r"(addr));
}
__device__ __forceinline__ void mma16816(float* d, uint32_t a0, uint32_t a1, uint32_t a2,
                                         uint32_t a3, uint32_t b0, uint32_t b1) {
    asm volatile(
        "mma.sync.aligned.m16n8k16.row.col.f32.f16.f16.f32 "
        "{%0,%1,%2,%3}, {%4,%5,%6,%7}, {%8,%9}, {%0,%1,%2,%3};"
        : "+f"(d[0]), "+f"(d[1]), "+f"(d[2]), "+f"(d[3])
        : "r"(a0), "r"(a1), "r"(a2), "r"(a3), "r"(b0), "r"(b1));
}
__device__ __forceinline__ void mma16808(float* d, uint32_t a0, uint32_t a1, uint32_t b0) {
    asm volatile(
        "mma.sync.aligned.m16n8k8.row.col.f32.f16.f16.f32 "
        "{%0,%1,%2,%3}, {%4,%5}, {%6}, {%0,%1,%2,%3};"
        : "+f"(d[0]), "+f"(d[1]), "+f"(d[2]), "+f"(d[3])
        : "r"(a0), "r"(a1), "r"(b0));
}
__device__ __forceinline__ void sts_u16(uint32_t addr, unsigned short v) {
    asm volatile("st.shared.u16 [%0], %1;" :: "r"(addr), "h"(v) : "memory");
}
__device__ __forceinline__ void sts_u32(uint32_t addr, uint32_t v) {
    asm volatile("st.shared.u32 [%0], %1;" :: "r"(addr), "r"(v) : "memory");
}
__device__ __forceinline__ void lds_v4(uint32_t addr, uint32_t& a, uint32_t& b,
                                       uint32_t& c, uint32_t& d) {
    asm volatile("ld.shared.v4.b32 {%0,%1,%2,%3}, [%4];"
                 : "=r"(a), "=r"(b), "=r"(c), "=r"(d) : "r"(addr));
}

// Fast 2^y: magic-constant round + deg-5 poly + exponent patch (no MUFU).
__device__ __forceinline__ float exp2_fast(float y) {
    const float magic = 12582912.0f;          // 2^23 + 2^22
    const float t = y + magic;
    const int   j = __float_as_int(t);
    const float f = y - (t - magic);          // f in [-0.5, 0.5]
    float p = 0.00133335581f;
    p = fmaf(p, f, 0.00961812911f);
    p = fmaf(p, f, 0.05550410866f);
    p = fmaf(p, f, 0.24022650696f);
    p = fmaf(p, f, 0.69314718056f);
    p = fmaf(p, f, 1.0f);
    return __int_as_float(__float_as_int(p) + (j << 23));
}

// ---------------------------------------------------------------------------
// R1: projection for 8 rows/warp -> scaled fp16 q8 into q8buf
// ---------------------------------------------------------------------------
__device__ __forceinline__ void regionR1(
    const float* __restrict__ query, char* smem, uint32_t q8buf,
    int warp, int lane, long row0)
{
    float* h4_s = (float*)(smem + SO_H4);
    const float4* w1v = (const float4*)(smem + SO_W1P + lane * 80);
    const float4 wa = w1v[0], wb = w1v[1], wc = w1v[2], wd2 = w1v[3];
    const float b1r = ((const float*)(smem + SO_B1))[lane];
    const int ci = lane & 7;
    const float b2r = ((const float*)(smem + SO_B2))[ci];
    const float4* w2v = (const float4*)(smem + SO_W2R + ci * 144);
    const float4* hv  = (const float4*)(h4_s + warp * 128);
    const int g = lane >> 3;

    #pragma unroll
    for (int g2 = 0; g2 < 2; g2++) {
        // pass 1: hidden layer for 4 rows
        #pragma unroll
        for (int rr = 0; rr < 4; rr++) {
            const long row = row0 + warp * 8 + g2 * 4 + rr;
            const float2* xp = (const float2*)(query + row * DQ);
            float xr[DQ];
            #pragma unroll
            for (int d = 0; d < 7; d++) {
                float2 v = __ldg(&xp[d]);
                xr[2 * d] = v.x; xr[2 * d + 1] = v.y;
            }
            float hj = b1r;
            hj = fmaf(wa.x, xr[0], hj);  hj = fmaf(wa.y, xr[1], hj);
            hj = fmaf(wa.z, xr[2], hj);  hj = fmaf(wa.w, xr[3], hj);
            hj = fmaf(wb.x, xr[4], hj);  hj = fmaf(wb.y, xr[5], hj);
            hj = fmaf(wb.z, xr[6], hj);  hj = fmaf(wb.w, xr[7], hj);
            hj = fmaf(wc.x, xr[8], hj);  hj = fmaf(wc.y, xr[9], hj);
            hj = fmaf(wc.z, xr[10], hj); hj = fmaf(wc.w, xr[11], hj);
            hj = fmaf(wd2.x, xr[12], hj); hj = fmaf(wd2.y, xr[13], hj);
            hj = 0.5f * hj * (1.0f + erff(hj * 0.7071067811865476f));
            h4_s[warp * 128 + rr * 32 + lane] = hj;
        }
        __syncwarp();

        // pass 2: q8, W2 fragments loaded once; store scaled fp16 q8
        {
            float q[4] = {b2r, b2r, b2r, b2r};
            #pragma unroll
            for (int j4 = 0; j4 < 8; j4++) {
                const float4 w4 = w2v[j4];
                #pragma unroll
                for (int rr = 0; rr < 4; rr++) {
                    const float4 h4 = hv[rr * 8 + j4];
                    q[rr] = fmaf(w4.x, h4.x, q[rr]);
                    q[rr] = fmaf(w4.y, h4.y, q[rr]);
                    q[rr] = fmaf(w4.z, h4.z, q[rr]);
                    q[rr] = fmaf(w4.w, h4.w, q[rr]);
                }
            }
            #pragma unroll
            for (int rr = 0; rr < 4; rr++) {
                float ss = q[rr] * q[rr];
                ss += __shfl_xor_sync(0xffffffffu, ss, 1);
                ss += __shfl_xor_sync(0xffffffffu, ss, 2);
                ss += __shfl_xor_sync(0xffffffffu, ss, 4);
                const float inv = CSCALE / fmaxf(sqrtf(ss), 1e-12f);
                const float qn = q[rr] * inv;
                if (g == rr)
                    sts_u16(q8buf + ((warp * 8 + g2 * 4 + rr) * 8 + ci) * 2,
                            __half_as_ushort(__float2half_rn(qn)));
            }
        }
        __syncwarp();
    }
}

// ---------------------------------------------------------------------------
// R3: attn out (vectorized) + content GEMM (32m x 64n warp tiles) + epilogue
// ---------------------------------------------------------------------------
__device__ __forceinline__ void regionR3(
    float* __restrict__ content, float* __restrict__ attn_out,
    uint32_t a_base, uint32_t b_base, const float* rsp_s,
    int warp, int lane, long row0)
{
    // ---- attn output: e * (1/rowsum) -> gmem (8 rows/warp, vectorized) ----
    // lane reads 4 consecutive u32 (8 halves) of e, writes 2 float4.
    const uint32_t a_row_base = a_base + (warp * 8) * (AK * 2);
    const bool alive = (lane < 30);          // 30 lanes cover 240 halves
    #pragma unroll
    for (int rr = 0; rr < 8; rr++) {
        const int r = warp * 8 + rr;
        const float rsum = rsp_s[r] + rsp_s[128 + r]
                         + rsp_s[256 + r] + rsp_s[384 + r];
        const float invs = __fdividef(1.0f, rsum);
        if (alive) {
            uint32_t v0, v1, v2, v3;
            lds_v4(a_row_base + rr * (AK * 2) + lane * 16, v0, v1, v2, v3);
            const float2 f0 = __half22float2(*(const __half2*)&v0);
            const float2 f1 = __half22float2(*(const __half2*)&v1);
            const float2 f2 = __half22float2(*(const __half2*)&v2);
            const float2 f3 = __half22float2(*(const __half2*)&v3);
            float* arow = attn_out + (row0 + r) * NS + lane * 8;
            float4 o0, o1;
            o0.x = f0.x * invs; o0.y = f0.y * invs;
            o0.z = f1.x * invs; o0.w = f1.y * invs;
            o1.x = f2.x * invs; o1.y = f2.y * invs;
            o1.z = f3.x * invs; o1.w = f3.y * invs;
            *(float4*)(arow)     = o0;
            *(float4*)(arow + 4) = o1;
        }
    }

    // ---- content = A(e) @ Bn^T, 32m x 64n warp tiles ----
    const int m0 = (warp & 3) * 32;
    const int n0 = (warp >> 2) * 64;

    float acc[2][8][4];
    #pragma unroll
    for (int i = 0; i < 2; i++)
        #pragma unroll
        for (int t = 0; t < 8; t++)
            #pragma unroll
            for (int j = 0; j < 4; j++) acc[i][t][j] = 0.f;

    const uint32_t a_lane0 = a_base
        + ((m0 + (lane & 15)) * AK + (lane >> 4) * 8) * 2;
    const uint32_t a_lane1 = a_lane0 + 16 * AK * 2;
    const uint32_t b_lane = b_base
        + ((n0 + ((lane >> 4) << 3) + (lane & 7)) * BKS
           + (((lane >> 3) & 1) * 8)) * 2;

    #pragma unroll
    for (int ks = 0; ks < NKSTEP; ks++) {
        uint32_t a0[4], a1[4];
        ldsm_x4(a0[0], a0[1], a0[2], a0[3], a_lane0 + ks * 32);
        ldsm_x4(a1[0], a1[1], a1[2], a1[3], a_lane1 + ks * 32);
        #pragma unroll
        for (int np = 0; np < 4; np++) {
            uint32_t b0, b1, b2, b3;
            ldsm_x4(b0, b1, b2, b3, b_lane + (np * 16 * BKS + ks * 16) * 2);
            mma16816(acc[0][2 * np],     a0[0], a0[1], a0[2], a0[3], b0, b1);
            mma16816(acc[0][2 * np + 1], a0[0], a0[1], a0[2], a0[3], b2, b3);
            mma16816(acc[1][2 * np],     a1[0], a1[1], a1[2], a1[3], b0, b1);
            mma16816(acc[1][2 * np + 1], a1[0], a1[1], a1[2], a1[3], b2, b3);
        }
    }

    // epilogue: scale by 1/rowsum (4 partials), store
    #pragma unroll
    for (int i = 0; i < 2; i++) {
        const int lrA = m0 + i * 16 + (lane >> 2);
        const float sA = rsp_s[lrA] + rsp_s[128 + lrA]
                       + rsp_s[256 + lrA] + rsp_s[384 + lrA];
        const int lrB = lrA + 8;
        const float sB = rsp_s[lrB] + rsp_s[128 + lrB]
                       + rsp_s[256 + lrB] + rsp_s[384 + lrB];
        const float invA = __fdividef(1.0f, sA);
        const float invB = __fdividef(1.0f, sB);
        const long r0 = row0 + lrA;
        const int cofs = (lane & 3) * 2;
        #pragma unroll
        for (int t = 0; t < 8; t++) {
            const int col = n0 + t * 8 + cofs;
            *(float2*)(content + r0 * DV + col) =
                make_float2(acc[i][t][0] * invA, acc[i][t][1] * invA);
            *(float2*)(content + (r0 + 8) * DV + col) =
                make_float2(acc[i][t][2] * invB, acc[i][t][3] * invB);
        }
    }
}

// ---------------------------------------------------------------------------
__global__ __launch_bounds__(NTHREADS, 1) void fused_kernel(
    const float* __restrict__ query,
    const float* __restrict__ W1, const float* __restrict__ b1,
    const float* __restrict__ W2, const float* __restrict__ b2,
    const float* __restrict__ values,
    const float* __restrict__ keys,
    float* __restrict__ content,
    float* __restrict__ attn_out,
    int nrows, int ntiles)
{
    extern __shared__ char smem[];
    float* rsp_s  = (float*)(smem + SO_RSP);

    const uint32_t smem_base = smem_u32(smem);
    const uint32_t a_base  = smem_base + SO_A;
    const uint32_t b_base  = smem_base + SO_B;
    const uint32_t k_base  = smem_base + SO_KEYH;
    const uint32_t q8_base = smem_base + SO_Q8S;

    const int tid  = threadIdx.x;
    const int warp = tid >> 5;
    const int lane = tid & 31;

    // ---- one-time setup ----
    {
        float* W1p = (float*)(smem + SO_W1P);
        for (int i = tid; i < HID * 20; i += NTHREADS) {
            int r = i / 20, d = i % 20;
            W1p[i] = (d < DQ) ? W1[r * DQ + d] : 0.f;
        }
        float* B1s = (float*)(smem + SO_B1);
        for (int i = tid; i < HID; i += NTHREADS) B1s[i] = b1[i];
        float* W2r = (float*)(smem + SO_W2R);
        for (int i = tid; i < DK * 36; i += NTHREADS) {
            int r = i / 36, j = i % 36;
            W2r[i] = (j < HID) ? W2[r * HID + j] : 0.f;
        }
        float* B2s = (float*)(smem + SO_B2);
        for (int i = tid; i < DK; i += NTHREADS) B2s[i] = b2[i];
        // exact fp16 keys: keys_n * sqrt(2) = E8 roots, components {0,+-1,+-0.5}
        for (int i = tid; i < 256 * DK; i += NTHREADS) {
            int k = i / DK, c = i % DK;
            float v = (k < NS) ? keys[k * DK + c] * 1.41421356237f : 0.f;
            sts_u16(k_base + i * 2, __half_as_ushort(__float2half_rn(v)));
        }
        // Bn[n][k] fp16 (n-major transpose of values[k][n])
        for (int i = tid; i < NS * (DV / 2); i += NTHREADS) {
            const int k  = i / (DV / 2);
            const int np = i % (DV / 2);
            const float2 v = __ldg((const float2*)(values + k * DV + 2 * np));
            sts_u16(b_base + ((2 * np)     * BKS + k) * 2,
                    __half_as_ushort(__float2half_rn(v.x)));
            sts_u16(b_base + ((2 * np + 1) * BKS + k) * 2,
                    __half_as_ushort(__float2half_rn(v.y)));
        }
    }
    __syncthreads();

    // ---- hoist key fragments (constant across tiles): 16 regs/warp ----
    const int nhalf = warp >> 3;             // 2 halves of 128 keys
    uint32_t kbf[2][8];
    #pragma unroll
    for (int nb2 = 0; nb2 < 2; nb2++) {
        const int n0s = (nhalf * 2 + nb2) * 64;
        ldsm_x4(kbf[nb2][0], kbf[nb2][1], kbf[nb2][2], kbf[nb2][3],
                k_base + (n0s + lane) * 16);
        ldsm_x4(kbf[nb2][4], kbf[nb2][5], kbf[nb2][6], kbf[nb2][7],
                k_base + (n0s + 32 + lane) * 16);
    }

    // ---- prologue: R1 of this CTA's first tile into q8 buf 0 ----
    regionR1(query, smem, q8_base, warp, lane, (long)blockIdx.x * TILE_M);
    __syncthreads();

    int i = 0;
    for (long t = blockIdx.x; t < ntiles; t += gridDim.x, i++) {
        const long row0 = t * TILE_M;
        const uint32_t q8cur = q8_base + (i & 1) * 2048;
        const uint32_t q8nxt = q8_base + ((i & 1) ^ 1) * 2048;

        // ====== R2: sim GEMM + exp + e->A tile + row partials ==============
        {
            const int mband = warp & 7;          // 8 bands of 16 rows
            const int m0s = mband * 16;

            uint32_t qa0, qa1;
            ldsm_x2(qa0, qa1, q8cur + (m0s + (lane & 15)) * 16);

            #pragma unroll
            for (int nb2 = 0; nb2 < 2; nb2++) {
                const int nband = nhalf * 2 + nb2;
                const int n0s = nband * 64;

                float d[8][4];
                #pragma unroll
                for (int tt = 0; tt < 8; tt++) {
                    d[tt][0] = d[tt][1] = d[tt][2] = d[tt][3] = 0.f;
                    mma16808(d[tt], qa0, qa1, kbf[nb2][tt]);
                }

                const int rA = m0s + (lane >> 2);
                const uint32_t arow0 = a_base + rA * (AK * 2)
                                     + (n0s + (lane & 3) * 2) * 2;
                const uint32_t arow1 = arow0 + 8 * (AK * 2);
                float sL = 0.f, sH = 0.f;
                const int tmax = (nband == 3) ? 6 : 8;   // mask keys >= 240
                #pragma unroll
                for (int tt = 0; tt < 8; tt++) {
                    if (tt < tmax) {
                        const float e0 = exp2_fast(d[tt][0] - CLOG2E);
                        const float e1 = exp2_fast(d[tt][1] - CLOG2E);
                        const float e2 = exp2_fast(d[tt][2] - CLOG2E);
                        const float e3 = exp2_fast(d[tt][3] - CLOG2E);
                        const __half2 h01 = __floats2half2_rn(e0, e1);
                        const __half2 h23 = __floats2half2_rn(e2, e3);
                        sts_u32(arow0 + tt * 16, *(const uint32_t*)&h01);
                        sts_u32(arow1 + tt * 16, *(const uint32_t*)&h23);
                        sL += e0 + e1;
                        sH += e2 + e3;
                    }
                }
                sL += __shfl_xor_sync(0xffffffffu, sL, 1);
                sL += __shfl_xor_sync(0xffffffffu, sL, 2);
                sH += __shfl_xor_sync(0xffffffffu, sH, 1);
                sH += __shfl_xor_sync(0xffffffffu, sH, 2);
                if ((lane & 3) == 0) {
                    rsp_s[nband * 128 + rA] = sL;
                    rsp_s[nband * 128 + rA + 8] = sH;
                }
            }
        }
        __syncthreads();

        // ====== merged region: R3(t) and R1(t+grid), order alternating ====
        const long nt = t + gridDim.x;
        if (warp & 1) {
            if (nt < ntiles)
                regionR1(query, smem, q8nxt, warp, lane, nt * TILE_M);
            regionR3(content, attn_out, a_base, b_base, rsp_s, warp, lane, row0);
        } else {
            regionR3(content, attn_out, a_base, b_base, rsp_s, warp, lane, row0);
            if (nt < ntiles)
                regionR1(query, smem, q8nxt, warp, lane, nt * TILE_M);
        }
        __syncthreads();
    }
}

// ---------------------------------------------------------------------------
extern "C" void kernel_launch(void* const* d_in, const int* in_sizes, int n_in,
                              void* d_out, int out_size)
{
    const float* query  = (const float*)d_in[0];
    const float* W1     = (const float*)d_in[1];
    const float* b1     = (const float*)d_in[2];
    const float* W2     = (const float*)d_in[3];
    const float* b2     = (const float*)d_in[4];
    const float* values = (const float*)d_in[5];
    const float* keys   = (const float*)d_in[6];

    const int nrows  = in_sizes[0] / DQ;   // 262144
    const int ntiles = (nrows + TILE_M - 1) / TILE_M;

    float* out = (float*)d_out;
    float* content = out;
    float* attn;
    float* scratch;
    cudaGetSymbolAddress((void**)&scratch, g_attn_scratch);
    if ((long)out_size >= (long)nrows * (DV + NS)) {
        attn = out + (long)nrows * DV;
    } else {
        attn = scratch;
    }

    cudaFuncSetAttribute(fused_kernel, cudaFuncAttributeMaxDynamicSharedMemorySize,
                         SMEM_TOTAL);

    fused_kernel<<<152, NTHREADS, SMEM_TOTAL>>>(
        query, W1, b1, W2, b2, values, keys, content, attn, nrows, ntiles);
}